// round 15
// baseline (speedup 1.0000x reference)
#include <cuda_runtime.h>
#include <cuda_fp16.h>
#include <cstdint>

#define NN 50000
#define NE 600000
#define F  128
#define NT 4
#define NOUT 640        // [self(128) | Y_t(128)*4]
#define RS 136          // padded smem row stride (fp16 elems)
#define HALF_N 64
#define NHALF 10        // NOUT / HALF_N

typedef unsigned long long ull;

// ---------------- scratch (static device globals; no allocation) ------------
__device__ __half g_Y[(size_t)NN * NOUT];      // projected features (fp16)
__device__ int   g_cnt[NT * NN];               // per-(type,dst) in-degree
__device__ int   g_off[NN];                    // exclusive CSR offsets (per dst)
__device__ int   g_cursor[NN];                 // fill cursors (end = off + deg)
__device__ int   g_epk[NE];                    // packed (src<<2)|type, bucketed by dst
__device__ int   g_bsum[64];                   // block sums for scan
__device__ __half g_Ah[(size_t)NN * F];        // fp16 activations
__device__ __half g_W1[NOUT * F];              // [n][k] layout (K-major rows)
__device__ __half g_W2[NOUT * F];
__device__ float g_bb1[F];
__device__ float g_bb2[F];

// ---------------- weight prep: fold type-mean, round to fp16 ----------------
__global__ void prep_weights(const float* __restrict__ Ws1, const float* __restrict__ Wn1,
                             const float* __restrict__ b1,
                             const float* __restrict__ Ws2, const float* __restrict__ Wn2,
                             const float* __restrict__ b2) {
    int idx = blockIdx.x * blockDim.x + threadIdx.x;   // over NOUT*F = 81920
    if (idx >= NOUT * F) return;
    int j = idx / F, k = idx % F;    // output col j, input k  (stored [j][k])
    float w1, w2;
    if (j < F) {
        float a1 = 0.f, a2 = 0.f;
        #pragma unroll
        for (int t = 0; t < NT; t++) {
            a1 += Ws1[(t * F + k) * F + j];
            a2 += Ws2[(t * F + k) * F + j];
        }
        w1 = a1 * 0.25f; w2 = a2 * 0.25f;
    } else {
        int t  = (j - F) >> 7;
        int jj = (j - F) & 127;
        w1 = Wn1[(t * F + k) * F + jj] * 0.25f;
        w2 = Wn2[(t * F + k) * F + jj] * 0.25f;
    }
    g_W1[idx] = __float2half_rn(w1);
    g_W2[idx] = __float2half_rn(w2);
    if (idx < F) {
        float s1 = 0.f, s2 = 0.f;
        #pragma unroll
        for (int t = 0; t < NT; t++) { s1 += b1[t * F + idx]; s2 += b2[t * F + idx]; }
        g_bb1[idx] = s1 * 0.25f; g_bb2[idx] = s2 * 0.25f;
    }
}

// ---------------- fp32 -> fp16 conversion (x only) ---------------------------
__global__ void convert_f16(const float* __restrict__ A) {
    size_t i = ((size_t)blockIdx.x * 256 + threadIdx.x) * 8;
    if (i >= (size_t)NN * F) return;
    float4 u0 = *reinterpret_cast<const float4*>(A + i);
    float4 u1 = *reinterpret_cast<const float4*>(A + i + 4);
    __half2 h0 = __floats2half2_rn(u0.x, u0.y);
    __half2 h1 = __floats2half2_rn(u0.z, u0.w);
    __half2 h2 = __floats2half2_rn(u1.x, u1.y);
    __half2 h3 = __floats2half2_rn(u1.z, u1.w);
    *reinterpret_cast<uint4*>(g_Ah + i) =
        make_uint4(*reinterpret_cast<uint32_t*>(&h0), *reinterpret_cast<uint32_t*>(&h1),
                   *reinterpret_cast<uint32_t*>(&h2), *reinterpret_cast<uint32_t*>(&h3));
}

// ---------------- CSR build ---------------------------------------------------
__global__ void zero_cnt() {
    int i = blockIdx.x * blockDim.x + threadIdx.x;
    if (i < NT * NN) g_cnt[i] = 0;
}
__global__ void count_edges(const int* __restrict__ ei, const int* __restrict__ et) {
    int e = blockIdx.x * blockDim.x + threadIdx.x;
    if (e >= NE) return;
    atomicAdd(&g_cnt[et[e] * NN + ei[NE + e]], 1);
}

__global__ void scan_blocks() {
    __shared__ int wsum[32];
    int tid = threadIdx.x, lane = tid & 31, w = tid >> 5;
    int idx = blockIdx.x * 1024 + tid;
    int v = 0;
    if (idx < NN) {
        #pragma unroll
        for (int t = 0; t < NT; t++) v += g_cnt[t * NN + idx];
    }
    int x = v;
    #pragma unroll
    for (int o = 1; o < 32; o <<= 1) {
        int y = __shfl_up_sync(0xFFFFFFFFu, x, o);
        if (lane >= o) x += y;
    }
    if (lane == 31) wsum[w] = x;
    __syncthreads();
    if (w == 0) {
        int s = wsum[lane];
        #pragma unroll
        for (int o = 1; o < 32; o <<= 1) {
            int y = __shfl_up_sync(0xFFFFFFFFu, s, o);
            if (lane >= o) s += y;
        }
        wsum[lane] = s;
    }
    __syncthreads();
    int excl = x - v + (w > 0 ? wsum[w - 1] : 0);
    if (idx < NN) g_off[idx] = excl;
    if (tid == 0) g_bsum[blockIdx.x] = wsum[31];
}
__global__ void scan_bsums() {
    __shared__ int s[64];
    int tid = threadIdx.x;
    s[tid] = (tid < 49) ? g_bsum[tid] : 0;
    __syncthreads();
    #pragma unroll
    for (int o = 1; o < 64; o <<= 1) {
        int v = (tid >= o) ? s[tid - o] : 0;
        __syncthreads();
        s[tid] += v;
        __syncthreads();
    }
    if (tid < 49) g_bsum[tid] = (tid > 0) ? s[tid - 1] : 0;
}
__global__ void add_bsums() {
    int idx = blockIdx.x * 1024 + threadIdx.x;
    if (idx < NN) {
        int o = g_off[idx] + g_bsum[blockIdx.x];
        g_off[idx] = o;
        g_cursor[idx] = o;
    }
}

__global__ void fill_edges(const int* __restrict__ ei, const int* __restrict__ et) {
    int e = blockIdx.x * blockDim.x + threadIdx.x;
    if (e >= NE) return;
    int src = ei[e];
    int dst = ei[NE + e];
    int t = et[e];
    int pos = atomicAdd(&g_cursor[dst], 1);
    g_epk[pos] = (src << 2) | t;
}

// ---------------- mma.sync fp16 GEMM: Y[N,640] = A[N,128] @ W[128,640] --------
__device__ __forceinline__ void mma_f32acc(float* d, const uint32_t* a, const uint32_t* b) {
    asm volatile("mma.sync.aligned.m16n8k16.row.col.f32.f16.f16.f32 "
                 "{%0,%1,%2,%3}, {%4,%5,%6,%7}, {%8,%9}, {%0,%1,%2,%3};"
                 : "+f"(d[0]), "+f"(d[1]), "+f"(d[2]), "+f"(d[3])
                 : "r"(a[0]), "r"(a[1]), "r"(a[2]), "r"(a[3]),
                   "r"(b[0]), "r"(b[1]));
}
__device__ __forceinline__ void ldsm_x4(uint32_t* r, uint32_t saddr) {
    asm volatile("ldmatrix.sync.aligned.m8n8.x4.shared.b16 {%0,%1,%2,%3}, [%4];"
                 : "=r"(r[0]), "=r"(r[1]), "=r"(r[2]), "=r"(r[3]) : "r"(saddr));
}
__device__ __forceinline__ void cp16(void* dst, const void* src) {
    uint32_t d = (uint32_t)__cvta_generic_to_shared(dst);
    asm volatile("cp.async.cg.shared.global [%0], [%1], 16;" :: "r"(d), "l"(src));
}
#define CP_COMMIT() asm volatile("cp.async.commit_group;" ::: "memory")
#define CP_WAIT(n)  asm volatile("cp.async.wait_group %0;" :: "n"(n) : "memory")

__global__ __launch_bounds__(128, 3)
void gemm_tc(const __half* __restrict__ wmat,
             const float* __restrict__ bias, __half* __restrict__ Y) {
    extern __shared__ __half smem[];
    __half* As   = smem;                             // 128 x RS
    __half* Bbuf = As + 128 * RS;                    // 2 x (64 x RS)

    int tid = threadIdx.x, wid = tid >> 5, lane = tid & 31;
    int gid = lane >> 2, tig = lane & 3;
    int l8 = lane & 7, sel = lane >> 3;
    int wm = wid & 1, wn = wid >> 1;                 // warp tile rows wm*64, cols wn*32
    int m0 = blockIdx.x * 128;

    // --- resident A tile, loaded once via cp.async (16 chunks/thread) ---
    {
        bool full = (m0 + 128 <= NN);
        #pragma unroll
        for (int i = 0; i < 16; i++) {
            int lin = tid + i * 128;                 // 0..2047
            int r = lin >> 4, c = lin & 15;
            int gr = m0 + r;
            if (full || gr < NN)
                cp16(As + r * RS + c * 8, g_Ah + (size_t)gr * F + c * 8);
            else
                *reinterpret_cast<uint4*>(As + r * RS + c * 8) = make_uint4(0, 0, 0, 0);
        }
    }
    // --- B half-tile prefetch into buffer buf ---
    auto issue_B = [&](int s, int buf) {
        const __half* src = wmat + (size_t)s * HALF_N * F;
        __half* dst = Bbuf + buf * HALF_N * RS;
        #pragma unroll
        for (int i = 0; i < 8; i++) {
            int lin = tid + i * 128;                 // 0..1023
            int r = lin >> 4, c = lin & 15;
            cp16(dst + r * RS + c * 8, src + r * F + c * 8);
        }
        CP_COMMIT();
    };
    issue_B(0, 0);

    uint32_t sA = (uint32_t)__cvta_generic_to_shared(As);

    int a_r = (sel & 1) * 8 + l8;
    int a_k = (sel >> 1) * 8;
    int b_n = (sel >> 1) * 8 + l8;
    int b_k = (sel & 1) * 8;

    for (int s = 0; s < NHALF; s++) {
        int buf = s & 1;
        if (s + 1 < NHALF) {
            issue_B(s + 1, buf ^ 1);
            CP_WAIT(1);
        } else {
            CP_WAIT(0);
        }
        __syncthreads();                              // B(s) + A visible

        uint32_t sB = (uint32_t)__cvta_generic_to_shared(Bbuf + buf * HALF_N * RS);

        float acc[4][4][4];
        #pragma unroll
        for (int i = 0; i < 4; i++)
            #pragma unroll
            for (int j = 0; j < 4; j++)
                #pragma unroll
                for (int q = 0; q < 4; q++) acc[i][j][q] = 0.f;

        #pragma unroll
        for (int ks = 0; ks < 8; ks++) {
            int kb = ks * 16;
            uint32_t af[4][4];
            #pragma unroll
            for (int mf = 0; mf < 4; mf++) {
                uint32_t off = (uint32_t)(((wm * 64 + mf * 16 + a_r) * RS + kb + a_k) * 2);
                ldsm_x4(af[mf], sA + off);
            }
            uint32_t bf[2][4];
            #pragma unroll
            for (int g = 0; g < 2; g++) {
                uint32_t off = (uint32_t)(((wn * 32 + g * 16 + b_n) * RS + kb + b_k) * 2);
                ldsm_x4(bf[g], sB + off);
            }
            #pragma unroll
            for (int mf = 0; mf < 4; mf++)
                #pragma unroll
                for (int g = 0; g < 2; g++) {
                    mma_f32acc(acc[mf][g * 2],     af[mf], &bf[g][0]);
                    mma_f32acc(acc[mf][g * 2 + 1], af[mf], &bf[g][2]);
                }
        }

        // epilogue for this 64-col half: global cols s*64 .. s*64+63, fp16 store
        int gc0 = s * HALF_N;
        bool has_bias = (gc0 < F);
        #pragma unroll
        for (int nf = 0; nf < 4; nf++) {
            int gc = gc0 + wn * 32 + nf * 8 + tig * 2;
            float b0 = has_bias ? bias[gc]     : 0.f;
            float b1 = has_bias ? bias[gc + 1] : 0.f;
            #pragma unroll
            for (int mf = 0; mf < 4; mf++) {
                int row = m0 + wm * 64 + mf * 16 + gid;
                __half* base = Y + (size_t)row * NOUT + gc;
                if (row < NN) {
                    __half2 p = __floats2half2_rn(acc[mf][nf][0] + b0, acc[mf][nf][1] + b1);
                    *reinterpret_cast<uint32_t*>(base) = *reinterpret_cast<uint32_t*>(&p);
                }
                if (row + 8 < NN) {
                    __half2 p = __floats2half2_rn(acc[mf][nf][2] + b0, acc[mf][nf][3] + b1);
                    *reinterpret_cast<uint32_t*>(base + 8 * NOUT) = *reinterpret_cast<uint32_t*>(&p);
                }
            }
        }
        __syncthreads();   // all warps done reading buf before it is refilled at s+2
    }
}

// ---------------- aggregate: out[dst] = Yself[dst] + sum_e invc[t]*Yt[src] ----
// Half-warp per row: 16 lanes x 8 halves (uint4) cover 128 cols; 2 rows/warp
// doubles memory-level parallelism. fp32 accumulation, unroll-4.
// NORM=true: l2norm+relu -> fp16 g_Ah.
struct F8 { float4 a, b; };
__device__ __forceinline__ F8 ld_y8(const __half* p) {
    uint4 u = *reinterpret_cast<const uint4*>(p);
    float2 f0 = __half22float2(*reinterpret_cast<__half2*>(&u.x));
    float2 f1 = __half22float2(*reinterpret_cast<__half2*>(&u.y));
    float2 f2 = __half22float2(*reinterpret_cast<__half2*>(&u.z));
    float2 f3 = __half22float2(*reinterpret_cast<__half2*>(&u.w));
    F8 r;
    r.a = make_float4(f0.x, f0.y, f1.x, f1.y);
    r.b = make_float4(f2.x, f2.y, f3.x, f3.y);
    return r;
}
__device__ __forceinline__ void fma8(F8& d, float s, const F8& v) {
    d.a.x += s * v.a.x; d.a.y += s * v.a.y; d.a.z += s * v.a.z; d.a.w += s * v.a.w;
    d.b.x += s * v.b.x; d.b.y += s * v.b.y; d.b.z += s * v.b.z; d.b.w += s * v.b.w;
}

template <bool NORM>
__global__ void aggregate(float* __restrict__ outp) {
    int gtid = blockIdx.x * blockDim.x + threadIdx.x;
    int row = gtid >> 4;                 // half-warp per row
    int l16 = threadIdx.x & 15;
    if (row >= NN) return;

    float inv[NT];
    #pragma unroll
    for (int t = 0; t < NT; t++) {
        int c = __ldg(&g_cnt[t * NN + row]);
        inv[t] = 1.0f / (float)(c > 1 ? c : 1);
    }
    int beg = g_off[row];
    int end = g_cursor[row];

    F8 acc = ld_y8(g_Y + (size_t)row * NOUT + l16 * 8);

    int i = beg;
    for (; i + 4 <= end; i += 4) {
        int pk0 = __ldg(&g_epk[i]);
        int pk1 = __ldg(&g_epk[i + 1]);
        int pk2 = __ldg(&g_epk[i + 2]);
        int pk3 = __ldg(&g_epk[i + 3]);
        F8 v0 = ld_y8(g_Y + (size_t)(pk0 >> 2) * NOUT + ((pk0 & 3) + 1) * F + l16 * 8);
        F8 v1 = ld_y8(g_Y + (size_t)(pk1 >> 2) * NOUT + ((pk1 & 3) + 1) * F + l16 * 8);
        F8 v2 = ld_y8(g_Y + (size_t)(pk2 >> 2) * NOUT + ((pk2 & 3) + 1) * F + l16 * 8);
        F8 v3 = ld_y8(g_Y + (size_t)(pk3 >> 2) * NOUT + ((pk3 & 3) + 1) * F + l16 * 8);
        fma8(acc, inv[pk0 & 3], v0);
        fma8(acc, inv[pk1 & 3], v1);
        fma8(acc, inv[pk2 & 3], v2);
        fma8(acc, inv[pk3 & 3], v3);
    }
    for (; i < end; i++) {
        int pk = __ldg(&g_epk[i]);
        F8 v = ld_y8(g_Y + (size_t)(pk >> 2) * NOUT + ((pk & 3) + 1) * F + l16 * 8);
        fma8(acc, inv[pk & 3], v);
    }

    if (NORM) {
        float ss = acc.a.x * acc.a.x + acc.a.y * acc.a.y + acc.a.z * acc.a.z + acc.a.w * acc.a.w
                 + acc.b.x * acc.b.x + acc.b.y * acc.b.y + acc.b.z * acc.b.z + acc.b.w * acc.b.w;
        #pragma unroll
        for (int o = 8; o > 0; o >>= 1)
            ss += __shfl_xor_sync(0xFFFFFFFFu, ss, o);   // reduce within 16-lane half
        float invn = 1.0f / fmaxf(sqrtf(ss), 1e-12f);
        float f[8] = {acc.a.x, acc.a.y, acc.a.z, acc.a.w,
                      acc.b.x, acc.b.y, acc.b.z, acc.b.w};
        uint32_t hw[4];
        #pragma unroll
        for (int j = 0; j < 4; j++) {
            __half2 p = __floats2half2_rn(fmaxf(f[2 * j] * invn, 0.f),
                                          fmaxf(f[2 * j + 1] * invn, 0.f));
            hw[j] = *reinterpret_cast<uint32_t*>(&p);
        }
        *reinterpret_cast<uint4*>(g_Ah + (size_t)row * F + l16 * 8) =
            make_uint4(hw[0], hw[1], hw[2], hw[3]);
    } else {
        float* dst = outp + (size_t)row * F + l16 * 8;
        *reinterpret_cast<float4*>(dst)     = acc.a;
        *reinterpret_cast<float4*>(dst + 4) = acc.b;
    }
}

// ---------------- launch -------------------------------------------------------
extern "C" void kernel_launch(void* const* d_in, const int* in_sizes, int n_in,
                              void* d_out, int out_size) {
    const float* x   = (const float*)d_in[0];
    const float* Ws1 = (const float*)d_in[1];
    const float* Wn1 = (const float*)d_in[2];
    const float* b1  = (const float*)d_in[3];
    const float* Ws2 = (const float*)d_in[4];
    const float* Wn2 = (const float*)d_in[5];
    const float* b2  = (const float*)d_in[6];
    const int*   ei  = (const int*)d_in[7];
    const int*   et  = (const int*)d_in[8];
    float* out = (float*)d_out;

    void *p_Y, *p_bb1, *p_bb2, *p_W1, *p_W2;
    cudaGetSymbolAddress(&p_Y, g_Y);
    cudaGetSymbolAddress(&p_bb1, g_bb1);
    cudaGetSymbolAddress(&p_bb2, g_bb2);
    cudaGetSymbolAddress(&p_W1, g_W1);
    cudaGetSymbolAddress(&p_W2, g_W2);

    const int SMEM_GEMM = (128 * RS + 2 * HALF_N * RS) * (int)sizeof(__half);
    cudaFuncSetAttribute(gemm_tc, cudaFuncAttributeMaxDynamicSharedMemorySize, SMEM_GEMM);

    const int GM_BLOCKS = (NN + 127) / 128;         // 391
    const int AG_BLOCKS = (int)(((size_t)NN * 16 + 255) / 256);   // half-warp per row
    const int SCAN_BLOCKS = (NN + 1023) / 1024;     // 49
    const int CV_BLOCKS = (int)(((size_t)NN * F / 8 + 255) / 256);

    // --- fork a side stream for the CSR build (R13 structure) ---
    cudaStream_t s2;
    cudaStreamCreateWithFlags(&s2, cudaStreamNonBlocking);
    cudaEvent_t evFork, evJoin;
    cudaEventCreateWithFlags(&evFork, cudaEventDisableTiming);
    cudaEventCreateWithFlags(&evJoin, cudaEventDisableTiming);

    cudaEventRecord(evFork, 0);
    cudaStreamWaitEvent(s2, evFork, 0);

    // main stream: weight prep + activation convert + layer-1 GEMM
    prep_weights<<<(NOUT * F + 255) / 256, 256>>>(Ws1, Wn1, b1, Ws2, Wn2, b2);
    convert_f16<<<CV_BLOCKS, 256>>>(x);
    gemm_tc<<<GM_BLOCKS, 128, SMEM_GEMM>>>((const __half*)p_W1,
                                           (const float*)p_bb1, (__half*)p_Y);

    // side stream: CSR build (runs concurrently with gemm1)
    zero_cnt<<<(NT * NN + 255) / 256, 256, 0, s2>>>();
    count_edges<<<(NE + 255) / 256, 256, 0, s2>>>(ei, et);
    scan_blocks<<<SCAN_BLOCKS, 1024, 0, s2>>>();
    scan_bsums<<<1, 64, 0, s2>>>();
    add_bsums<<<SCAN_BLOCKS, 1024, 0, s2>>>();
    fill_edges<<<(NE + 255) / 256, 256, 0, s2>>>(ei, et);

    cudaEventRecord(evJoin, s2);
    cudaStreamWaitEvent(0, evJoin, 0);

    // join: aggregate layer 1 needs both gemm1 (Y) and CSR
    aggregate<true><<<AG_BLOCKS, 256>>>(nullptr);    // writes g_Ah fp16

    // ---- layer 2 ----
    gemm_tc<<<GM_BLOCKS, 128, SMEM_GEMM>>>((const __half*)p_W2,
                                           (const float*)p_bb2, (__half*)p_Y);
    aggregate<false><<<AG_BLOCKS, 256>>>(out);

    cudaStreamDestroy(s2);
    cudaEventDestroy(evFork);
    cudaEventDestroy(evJoin);
}

// round 16
// speedup vs baseline: 1.3345x; 1.3345x over previous
#include <cuda_runtime.h>
#include <cuda_fp16.h>
#include <cstdint>

#define NN 50000
#define NE 600000
#define F  128
#define NT 4
#define NOUT 640        // [self(128) | Y_t(128)*4]
#define RS 136          // padded smem row stride (fp16 elems)
#define HALF_N 64
#define NHALF 10        // NOUT / HALF_N

typedef unsigned long long ull;

// ---------------- scratch (static device globals; no allocation) ------------
__device__ __half g_Y[(size_t)NN * NOUT];      // projected features (fp16)
__device__ int   g_cnt[NT * NN];               // per-(type,dst) in-degree
__device__ int   g_off[NN];                    // exclusive CSR offsets (per dst)
__device__ int   g_cursor[NN];                 // fill cursors (end = off + deg)
__device__ int   g_epk[NE];                    // packed (src<<2)|type, bucketed by dst
__device__ int   g_bsum[64];                   // block sums for scan
__device__ __half g_Ah[(size_t)NN * F];        // fp16 activations
__device__ __half g_W1[NOUT * F];              // [n][k] layout (K-major rows)
__device__ __half g_W2[NOUT * F];
__device__ float g_bb1[F];
__device__ float g_bb2[F];

// ---------------- weight prep: fold type-mean, round to fp16 ----------------
__global__ void prep_weights(const float* __restrict__ Ws1, const float* __restrict__ Wn1,
                             const float* __restrict__ b1,
                             const float* __restrict__ Ws2, const float* __restrict__ Wn2,
                             const float* __restrict__ b2) {
    int idx = blockIdx.x * blockDim.x + threadIdx.x;   // over NOUT*F = 81920
    if (idx >= NOUT * F) return;
    int j = idx / F, k = idx % F;    // output col j, input k  (stored [j][k])
    float w1, w2;
    if (j < F) {
        float a1 = 0.f, a2 = 0.f;
        #pragma unroll
        for (int t = 0; t < NT; t++) {
            a1 += Ws1[(t * F + k) * F + j];
            a2 += Ws2[(t * F + k) * F + j];
        }
        w1 = a1 * 0.25f; w2 = a2 * 0.25f;
    } else {
        int t  = (j - F) >> 7;
        int jj = (j - F) & 127;
        w1 = Wn1[(t * F + k) * F + jj] * 0.25f;
        w2 = Wn2[(t * F + k) * F + jj] * 0.25f;
    }
    g_W1[idx] = __float2half_rn(w1);
    g_W2[idx] = __float2half_rn(w2);
    if (idx < F) {
        float s1 = 0.f, s2 = 0.f;
        #pragma unroll
        for (int t = 0; t < NT; t++) { s1 += b1[t * F + idx]; s2 += b2[t * F + idx]; }
        g_bb1[idx] = s1 * 0.25f; g_bb2[idx] = s2 * 0.25f;
    }
}

// ---------------- fp32 -> fp16 conversion (x only) ---------------------------
__global__ void convert_f16(const float* __restrict__ A) {
    size_t i = ((size_t)blockIdx.x * 256 + threadIdx.x) * 8;
    if (i >= (size_t)NN * F) return;
    float4 u0 = *reinterpret_cast<const float4*>(A + i);
    float4 u1 = *reinterpret_cast<const float4*>(A + i + 4);
    __half2 h0 = __floats2half2_rn(u0.x, u0.y);
    __half2 h1 = __floats2half2_rn(u0.z, u0.w);
    __half2 h2 = __floats2half2_rn(u1.x, u1.y);
    __half2 h3 = __floats2half2_rn(u1.z, u1.w);
    *reinterpret_cast<uint4*>(g_Ah + i) =
        make_uint4(*reinterpret_cast<uint32_t*>(&h0), *reinterpret_cast<uint32_t*>(&h1),
                   *reinterpret_cast<uint32_t*>(&h2), *reinterpret_cast<uint32_t*>(&h3));
}

// ---------------- CSR build ---------------------------------------------------
__global__ void zero_cnt() {
    int i = blockIdx.x * blockDim.x + threadIdx.x;
    if (i < NT * NN) g_cnt[i] = 0;
}
__global__ void count_edges(const int* __restrict__ ei, const int* __restrict__ et) {
    int e = blockIdx.x * blockDim.x + threadIdx.x;
    if (e >= NE) return;
    atomicAdd(&g_cnt[et[e] * NN + ei[NE + e]], 1);
}

__global__ void scan_blocks() {
    __shared__ int wsum[32];
    int tid = threadIdx.x, lane = tid & 31, w = tid >> 5;
    int idx = blockIdx.x * 1024 + tid;
    int v = 0;
    if (idx < NN) {
        #pragma unroll
        for (int t = 0; t < NT; t++) v += g_cnt[t * NN + idx];
    }
    int x = v;
    #pragma unroll
    for (int o = 1; o < 32; o <<= 1) {
        int y = __shfl_up_sync(0xFFFFFFFFu, x, o);
        if (lane >= o) x += y;
    }
    if (lane == 31) wsum[w] = x;
    __syncthreads();
    if (w == 0) {
        int s = wsum[lane];
        #pragma unroll
        for (int o = 1; o < 32; o <<= 1) {
            int y = __shfl_up_sync(0xFFFFFFFFu, s, o);
            if (lane >= o) s += y;
        }
        wsum[lane] = s;
    }
    __syncthreads();
    int excl = x - v + (w > 0 ? wsum[w - 1] : 0);
    if (idx < NN) g_off[idx] = excl;
    if (tid == 0) g_bsum[blockIdx.x] = wsum[31];
}
__global__ void scan_bsums() {
    __shared__ int s[64];
    int tid = threadIdx.x;
    s[tid] = (tid < 49) ? g_bsum[tid] : 0;
    __syncthreads();
    #pragma unroll
    for (int o = 1; o < 64; o <<= 1) {
        int v = (tid >= o) ? s[tid - o] : 0;
        __syncthreads();
        s[tid] += v;
        __syncthreads();
    }
    if (tid < 49) g_bsum[tid] = (tid > 0) ? s[tid - 1] : 0;
}
__global__ void add_bsums() {
    int idx = blockIdx.x * 1024 + threadIdx.x;
    if (idx < NN) {
        int o = g_off[idx] + g_bsum[blockIdx.x];
        g_off[idx] = o;
        g_cursor[idx] = o;
    }
}

__global__ void fill_edges(const int* __restrict__ ei, const int* __restrict__ et) {
    int e = blockIdx.x * blockDim.x + threadIdx.x;
    if (e >= NE) return;
    int src = ei[e];
    int dst = ei[NE + e];
    int t = et[e];
    int pos = atomicAdd(&g_cursor[dst], 1);
    g_epk[pos] = (src << 2) | t;
}

// ---------------- mma.sync fp16 GEMM: Y[N,640] = A[N,128] @ W[128,640] --------
__device__ __forceinline__ void mma_f32acc(float* d, const uint32_t* a, const uint32_t* b) {
    asm volatile("mma.sync.aligned.m16n8k16.row.col.f32.f16.f16.f32 "
                 "{%0,%1,%2,%3}, {%4,%5,%6,%7}, {%8,%9}, {%0,%1,%2,%3};"
                 : "+f"(d[0]), "+f"(d[1]), "+f"(d[2]), "+f"(d[3])
                 : "r"(a[0]), "r"(a[1]), "r"(a[2]), "r"(a[3]),
                   "r"(b[0]), "r"(b[1]));
}
__device__ __forceinline__ void ldsm_x4(uint32_t* r, uint32_t saddr) {
    asm volatile("ldmatrix.sync.aligned.m8n8.x4.shared.b16 {%0,%1,%2,%3}, [%4];"
                 : "=r"(r[0]), "=r"(r[1]), "=r"(r[2]), "=r"(r[3]) : "r"(saddr));
}
__device__ __forceinline__ void cp16(void* dst, const void* src) {
    uint32_t d = (uint32_t)__cvta_generic_to_shared(dst);
    asm volatile("cp.async.cg.shared.global [%0], [%1], 16;" :: "r"(d), "l"(src));
}
#define CP_COMMIT() asm volatile("cp.async.commit_group;" ::: "memory")
#define CP_WAIT(n)  asm volatile("cp.async.wait_group %0;" :: "n"(n) : "memory")

__global__ __launch_bounds__(128, 3)
void gemm_tc(const __half* __restrict__ wmat,
             const float* __restrict__ bias, __half* __restrict__ Y) {
    extern __shared__ __half smem[];
    __half* As   = smem;                             // 128 x RS
    __half* Bbuf = As + 128 * RS;                    // 2 x (64 x RS)

    int tid = threadIdx.x, wid = tid >> 5, lane = tid & 31;
    int gid = lane >> 2, tig = lane & 3;
    int l8 = lane & 7, sel = lane >> 3;
    int wm = wid & 1, wn = wid >> 1;                 // warp tile rows wm*64, cols wn*32
    int m0 = blockIdx.x * 128;

    // --- resident A tile, loaded once via cp.async (16 chunks/thread) ---
    {
        bool full = (m0 + 128 <= NN);
        #pragma unroll
        for (int i = 0; i < 16; i++) {
            int lin = tid + i * 128;                 // 0..2047
            int r = lin >> 4, c = lin & 15;
            int gr = m0 + r;
            if (full || gr < NN)
                cp16(As + r * RS + c * 8, g_Ah + (size_t)gr * F + c * 8);
            else
                *reinterpret_cast<uint4*>(As + r * RS + c * 8) = make_uint4(0, 0, 0, 0);
        }
    }
    // --- B half-tile prefetch into buffer buf ---
    auto issue_B = [&](int s, int buf) {
        const __half* src = wmat + (size_t)s * HALF_N * F;
        __half* dst = Bbuf + buf * HALF_N * RS;
        #pragma unroll
        for (int i = 0; i < 8; i++) {
            int lin = tid + i * 128;                 // 0..1023
            int r = lin >> 4, c = lin & 15;
            cp16(dst + r * RS + c * 8, src + r * F + c * 8);
        }
        CP_COMMIT();
    };
    issue_B(0, 0);

    uint32_t sA = (uint32_t)__cvta_generic_to_shared(As);

    int a_r = (sel & 1) * 8 + l8;
    int a_k = (sel >> 1) * 8;
    int b_n = (sel >> 1) * 8 + l8;
    int b_k = (sel & 1) * 8;

    for (int s = 0; s < NHALF; s++) {
        int buf = s & 1;
        if (s + 1 < NHALF) {
            issue_B(s + 1, buf ^ 1);
            CP_WAIT(1);
        } else {
            CP_WAIT(0);
        }
        __syncthreads();                              // B(s) + A visible

        uint32_t sB = (uint32_t)__cvta_generic_to_shared(Bbuf + buf * HALF_N * RS);

        float acc[4][4][4];
        #pragma unroll
        for (int i = 0; i < 4; i++)
            #pragma unroll
            for (int j = 0; j < 4; j++)
                #pragma unroll
                for (int q = 0; q < 4; q++) acc[i][j][q] = 0.f;

        #pragma unroll
        for (int ks = 0; ks < 8; ks++) {
            int kb = ks * 16;
            uint32_t af[4][4];
            #pragma unroll
            for (int mf = 0; mf < 4; mf++) {
                uint32_t off = (uint32_t)(((wm * 64 + mf * 16 + a_r) * RS + kb + a_k) * 2);
                ldsm_x4(af[mf], sA + off);
            }
            uint32_t bf[2][4];
            #pragma unroll
            for (int g = 0; g < 2; g++) {
                uint32_t off = (uint32_t)(((wn * 32 + g * 16 + b_n) * RS + kb + b_k) * 2);
                ldsm_x4(bf[g], sB + off);
            }
            #pragma unroll
            for (int mf = 0; mf < 4; mf++)
                #pragma unroll
                for (int g = 0; g < 2; g++) {
                    mma_f32acc(acc[mf][g * 2],     af[mf], &bf[g][0]);
                    mma_f32acc(acc[mf][g * 2 + 1], af[mf], &bf[g][2]);
                }
        }

        // epilogue for this 64-col half: global cols s*64 .. s*64+63, fp16 store
        int gc0 = s * HALF_N;
        bool has_bias = (gc0 < F);
        #pragma unroll
        for (int nf = 0; nf < 4; nf++) {
            int gc = gc0 + wn * 32 + nf * 8 + tig * 2;
            float b0 = has_bias ? bias[gc]     : 0.f;
            float b1 = has_bias ? bias[gc + 1] : 0.f;
            #pragma unroll
            for (int mf = 0; mf < 4; mf++) {
                int row = m0 + wm * 64 + mf * 16 + gid;
                __half* base = Y + (size_t)row * NOUT + gc;
                if (row < NN) {
                    __half2 p = __floats2half2_rn(acc[mf][nf][0] + b0, acc[mf][nf][1] + b1);
                    *reinterpret_cast<uint32_t*>(base) = *reinterpret_cast<uint32_t*>(&p);
                }
                if (row + 8 < NN) {
                    __half2 p = __floats2half2_rn(acc[mf][nf][2] + b0, acc[mf][nf][3] + b1);
                    *reinterpret_cast<uint32_t*>(base + 8 * NOUT) = *reinterpret_cast<uint32_t*>(&p);
                }
            }
        }
        __syncthreads();   // all warps done reading buf before it is refilled at s+2
    }
}

// ---------------- aggregate: out[dst] = Yself[dst] + sum_e invc[t]*Yt[src] ----
// Warp per row (R13 layout). Y is fp16; accumulation in fp32, unroll-4.
// NORM=true: l2norm+relu -> fp16 g_Ah.
__device__ __forceinline__ float4 ld_y4(const __half* p) {
    uint2 u = *reinterpret_cast<const uint2*>(p);
    float2 a = __half22float2(*reinterpret_cast<__half2*>(&u.x));
    float2 b = __half22float2(*reinterpret_cast<__half2*>(&u.y));
    return make_float4(a.x, a.y, b.x, b.y);
}

template <bool NORM>
__global__ void aggregate(float* __restrict__ outp) {
    int gtid = blockIdx.x * blockDim.x + threadIdx.x;
    int row = gtid >> 5;
    int lane = threadIdx.x & 31;
    if (row >= NN) return;

    float inv[NT];
    #pragma unroll
    for (int t = 0; t < NT; t++) {
        int c = __ldg(&g_cnt[t * NN + row]);
        inv[t] = 1.0f / (float)(c > 1 ? c : 1);
    }
    int beg = g_off[row];
    int end = g_cursor[row];

    float4 acc = ld_y4(g_Y + (size_t)row * NOUT + lane * 4);

    int i = beg;
    for (; i + 4 <= end; i += 4) {
        int pk0 = __ldg(&g_epk[i]);
        int pk1 = __ldg(&g_epk[i + 1]);
        int pk2 = __ldg(&g_epk[i + 2]);
        int pk3 = __ldg(&g_epk[i + 3]);
        float4 v0 = ld_y4(g_Y + (size_t)(pk0 >> 2) * NOUT + ((pk0 & 3) + 1) * F + lane * 4);
        float4 v1 = ld_y4(g_Y + (size_t)(pk1 >> 2) * NOUT + ((pk1 & 3) + 1) * F + lane * 4);
        float4 v2 = ld_y4(g_Y + (size_t)(pk2 >> 2) * NOUT + ((pk2 & 3) + 1) * F + lane * 4);
        float4 v3 = ld_y4(g_Y + (size_t)(pk3 >> 2) * NOUT + ((pk3 & 3) + 1) * F + lane * 4);
        float s0 = inv[pk0 & 3], s1 = inv[pk1 & 3], s2 = inv[pk2 & 3], s3 = inv[pk3 & 3];
        acc.x += s0 * v0.x; acc.y += s0 * v0.y; acc.z += s0 * v0.z; acc.w += s0 * v0.w;
        acc.x += s1 * v1.x; acc.y += s1 * v1.y; acc.z += s1 * v1.z; acc.w += s1 * v1.w;
        acc.x += s2 * v2.x; acc.y += s2 * v2.y; acc.z += s2 * v2.z; acc.w += s2 * v2.w;
        acc.x += s3 * v3.x; acc.y += s3 * v3.y; acc.z += s3 * v3.z; acc.w += s3 * v3.w;
    }
    for (; i < end; i++) {
        int pk = __ldg(&g_epk[i]);
        float4 v = ld_y4(g_Y + (size_t)(pk >> 2) * NOUT + ((pk & 3) + 1) * F + lane * 4);
        float s = inv[pk & 3];
        acc.x += s * v.x; acc.y += s * v.y; acc.z += s * v.z; acc.w += s * v.w;
    }

    if (NORM) {
        float ss = acc.x * acc.x + acc.y * acc.y + acc.z * acc.z + acc.w * acc.w;
        #pragma unroll
        for (int o = 16; o > 0; o >>= 1)
            ss += __shfl_xor_sync(0xFFFFFFFFu, ss, o);
        float invn = 1.0f / fmaxf(sqrtf(ss), 1e-12f);
        acc.x = fmaxf(acc.x * invn, 0.f);
        acc.y = fmaxf(acc.y * invn, 0.f);
        acc.z = fmaxf(acc.z * invn, 0.f);
        acc.w = fmaxf(acc.w * invn, 0.f);
        __half2 h0 = __floats2half2_rn(acc.x, acc.y);
        __half2 h1 = __floats2half2_rn(acc.z, acc.w);
        size_t o = (size_t)row * F + lane * 4;
        *reinterpret_cast<uint2*>(g_Ah + o) =
            make_uint2(*reinterpret_cast<uint32_t*>(&h0), *reinterpret_cast<uint32_t*>(&h1));
    } else {
        *(reinterpret_cast<float4*>(outp + (size_t)row * F) + lane) = acc;
    }
}

// ---------------- launch -------------------------------------------------------
extern "C" void kernel_launch(void* const* d_in, const int* in_sizes, int n_in,
                              void* d_out, int out_size) {
    const float* x   = (const float*)d_in[0];
    const float* Ws1 = (const float*)d_in[1];
    const float* Wn1 = (const float*)d_in[2];
    const float* b1  = (const float*)d_in[3];
    const float* Ws2 = (const float*)d_in[4];
    const float* Wn2 = (const float*)d_in[5];
    const float* b2  = (const float*)d_in[6];
    const int*   ei  = (const int*)d_in[7];
    const int*   et  = (const int*)d_in[8];
    float* out = (float*)d_out;

    void *p_Y, *p_bb1, *p_bb2, *p_W1, *p_W2;
    cudaGetSymbolAddress(&p_Y, g_Y);
    cudaGetSymbolAddress(&p_bb1, g_bb1);
    cudaGetSymbolAddress(&p_bb2, g_bb2);
    cudaGetSymbolAddress(&p_W1, g_W1);
    cudaGetSymbolAddress(&p_W2, g_W2);

    const int SMEM_GEMM = (128 * RS + 2 * HALF_N * RS) * (int)sizeof(__half);
    cudaFuncSetAttribute(gemm_tc, cudaFuncAttributeMaxDynamicSharedMemorySize, SMEM_GEMM);

    const int GM_BLOCKS = (NN + 127) / 128;         // 391
    const int AG_BLOCKS = (int)(((size_t)NN * 32 + 255) / 256);
    const int SCAN_BLOCKS = (NN + 1023) / 1024;     // 49
    const int CV_BLOCKS = (int)(((size_t)NN * F / 8 + 255) / 256);

    // --- side stream: prep_weights (needed by gemm1) then CSR build ---
    cudaStream_t s2;
    cudaStreamCreateWithFlags(&s2, cudaStreamNonBlocking);
    cudaEvent_t evFork, evPrep, evJoin;
    cudaEventCreateWithFlags(&evFork, cudaEventDisableTiming);
    cudaEventCreateWithFlags(&evPrep, cudaEventDisableTiming);
    cudaEventCreateWithFlags(&evJoin, cudaEventDisableTiming);

    cudaEventRecord(evFork, 0);
    cudaStreamWaitEvent(s2, evFork, 0);

    // s2: prep (overlaps convert), then CSR chain (overlaps gemm1)
    prep_weights<<<(NOUT * F + 255) / 256, 256, 0, s2>>>(Ws1, Wn1, b1, Ws2, Wn2, b2);
    cudaEventRecord(evPrep, s2);
    zero_cnt<<<(NT * NN + 255) / 256, 256, 0, s2>>>();
    count_edges<<<(NE + 255) / 256, 256, 0, s2>>>(ei, et);
    scan_blocks<<<SCAN_BLOCKS, 1024, 0, s2>>>();
    scan_bsums<<<1, 64, 0, s2>>>();
    add_bsums<<<SCAN_BLOCKS, 1024, 0, s2>>>();
    fill_edges<<<(NE + 255) / 256, 256, 0, s2>>>(ei, et);
    cudaEventRecord(evJoin, s2);

    // main: convert (|| prep), wait for weights, gemm1 (|| CSR)
    convert_f16<<<CV_BLOCKS, 256>>>(x);
    cudaStreamWaitEvent(0, evPrep, 0);
    gemm_tc<<<GM_BLOCKS, 128, SMEM_GEMM>>>((const __half*)p_W1,
                                           (const float*)p_bb1, (__half*)p_Y);

    cudaStreamWaitEvent(0, evJoin, 0);

    // join: aggregate layer 1 needs both gemm1 (Y) and CSR
    aggregate<true><<<AG_BLOCKS, 256>>>(nullptr);    // writes g_Ah fp16

    // ---- layer 2 ----
    gemm_tc<<<GM_BLOCKS, 128, SMEM_GEMM>>>((const __half*)p_W2,
                                           (const float*)p_bb2, (__half*)p_Y);
    aggregate<false><<<AG_BLOCKS, 256>>>(out);

    cudaStreamDestroy(s2);
    cudaEventDestroy(evFork);
    cudaEventDestroy(evPrep);
    cudaEventDestroy(evJoin);
}